// round 10
// baseline (speedup 1.0000x reference)
#include <cuda_runtime.h>
#include <cuda_fp16.h>
#include <cstdint>

// RNNModel: g = [E|R]@[We|Wr]^T + (be+br+bh)  (proj, relu on t==0 rows)
//           h_t = relu(g_t + h_{t-1}@Wh^T)    (7 in-place GEMM launches)
//           need = h_7^T
// R8: fragment double-buffering (LDSM ks+1 under MMA ks) + single barrier per
//     K-tile (mid-tile wait, next-tile frag prefetch under last MMA burst).
//     CTA tile 256x128, warp tile 64x64, fp16 gmem operands, 3-stage cp.async.
// NOTE: tcgen05 unusable in this harness build (ptxas targets compute_103 base).

#define STAGES    3
#define SROWB     144                   // bytes per smem row (64 halfs + pad)
#define A_STAGE_B (256 * SROWB)         // 36864
#define B_STAGE_B (128 * SROWB)         // 18432
#define A_REGION  (STAGES * A_STAGE_B)  // 110592
#define SMEM_SZ   (A_REGION + STAGES * B_STAGE_B + 512)   // 166400

// fp16 scratch (device-global: allocation-free)
__device__ __half g_A16[(size_t)65536 * 1536];   // packed [E|R]
__device__ __half g_W16[1024 * 1536];            // packed [We|Wr]
__device__ __half g_Wh16[1024 * 1024];
__device__ __half g_H16[(size_t)65536 * 1024];   // h_t fp16, same row indexing as out

__device__ __forceinline__ void mma_f16(float c[4], const unsigned a[4], const unsigned b[2]) {
    asm volatile(
        "mma.sync.aligned.m16n8k16.row.col.f32.f16.f16.f32 "
        "{%0,%1,%2,%3}, {%4,%5,%6,%7}, {%8,%9}, {%0,%1,%2,%3};\n"
        : "+f"(c[0]), "+f"(c[1]), "+f"(c[2]), "+f"(c[3])
        : "r"(a[0]), "r"(a[1]), "r"(a[2]), "r"(a[3]),
          "r"(b[0]), "r"(b[1]));
}
__device__ __forceinline__ void ldsm_x4(unsigned& r0, unsigned& r1, unsigned& r2, unsigned& r3,
                                        unsigned addr) {
    asm volatile("ldmatrix.sync.aligned.m8n8.x4.shared.b16 {%0,%1,%2,%3}, [%4];\n"
                 : "=r"(r0), "=r"(r1), "=r"(r2), "=r"(r3)
                 : "r"(addr));
}
__device__ __forceinline__ void cp16(unsigned dst, const void* src) {
    asm volatile("cp.async.cg.shared.global [%0], [%1], 16;" :: "r"(dst), "l"(src));
}
__device__ __forceinline__ void cp_commit() {
    asm volatile("cp.async.commit_group;" ::: "memory");
}
__device__ __forceinline__ void cp_wait0() {
    asm volatile("cp.async.wait_group 0;" ::: "memory");
}
__device__ __forceinline__ void cp_wait1() {
    asm volatile("cp.async.wait_group 1;" ::: "memory");
}

// MODE 0: C[65536,1024] = A16 @ W16^T + bias; relu + H16 write on rows%8==0.
// MODE 1: C(+t*1024 by host) = relu(C + H16(t-1) @ Wh16^T); writes H16(t).
template<int MODE>
__global__ __launch_bounds__(256, 1)
void gemm16(int t, const float* __restrict__ be, const float* __restrict__ br,
            const float* __restrict__ bhp, float* C)
{
    constexpr int KTOT = MODE ? 1024 : 1536;
    constexpr int NKT  = KTOT / 64;
    constexpr int LDA  = MODE ? 8192 : 1536;
    constexpr int LDB  = MODE ? 1024 : 1536;
    constexpr int LDC  = MODE ? 8192 : 1024;

    extern __shared__ __align__(16) char sm[];
    float* sBias = (float*)(sm + A_REGION + STAGES * B_STAGE_B);
    const unsigned smBase = (unsigned)__cvta_generic_to_shared(sm);

    const int tid = threadIdx.x;
    const int bN  = blockIdx.x;
    const int bM  = blockIdx.y;

    const __half* A = MODE ? g_H16 + (size_t)(t - 1) * 1024 : g_A16;
    const __half* B = MODE ? g_Wh16 : g_W16;
    __half* Hout = MODE ? g_H16 + (size_t)t * 1024 : g_H16;
    const int ldH = MODE ? 8192 : 1024;

    if (MODE == 0) {
        if (tid < 128) {
            int c = bN * 128 + tid;
            sBias[tid] = be[c] + br[c] + bhp[c];
        }
    }

    const int lane = tid & 31;
    const int warp = tid >> 5;
    const int wm = warp & 3;      // 4 M-warps of 64 rows
    const int wn = warp >> 2;     // 2 N-warps of 64 cols
    const int g8  = lane >> 2;    // 0..7
    const int qid = lane & 3;

    auto stageLoad = [&](int kt) {
        const int st = kt % STAGES;
        const unsigned dA = smBase + st * A_STAGE_B;
        const unsigned dB = smBase + A_REGION + st * B_STAGE_B;
        const int gk0 = kt * 64;
        #pragma unroll
        for (int i = 0; i < 8; ++i) {
            int c = tid + i * 256;
            int row = c >> 3, ch = c & 7;
            cp16(dA + row * SROWB + ch * 16,
                 A + (size_t)(bM * 256 + row) * LDA + gk0 + ch * 8);
        }
        #pragma unroll
        for (int i = 0; i < 4; ++i) {
            int c = tid + i * 256;
            int row = c >> 3, ch = c & 7;
            cp16(dB + row * SROWB + ch * 16,
                 B + (size_t)(bN * 128 + row) * LDB + gk0 + ch * 8);
        }
        cp_commit();
    };

    // ldmatrix base addresses (stage 0)
    const int rA = wm * 64 + (lane & 7) + ((lane >> 3) & 1) * 8;
    const int kselA = (lane >> 4) & 1;
    unsigned aAddr[4];
    #pragma unroll
    for (int mt = 0; mt < 4; ++mt)
        aAddr[mt] = smBase + (unsigned)((rA + mt * 16) * SROWB + kselA * 16);
    const int rB = wn * 64 + (lane & 7) + ((lane >> 4) & 1) * 8;
    const int kselB = (lane >> 3) & 1;
    unsigned bAddr[4];
    #pragma unroll
    for (int p = 0; p < 4; ++p)
        bAddr[p] = smBase + (unsigned)(A_REGION + (rB + p * 16) * SROWB + kselB * 16);

    // fragment double buffer
    unsigned af0[4][4], af1[4][4], bf0[8][2], bf1[8][2];

    auto ldF = [&](unsigned (&af)[4][4], unsigned (&bf)[8][2], unsigned offA, unsigned offB) {
        #pragma unroll
        for (int mt = 0; mt < 4; ++mt)
            ldsm_x4(af[mt][0], af[mt][1], af[mt][2], af[mt][3], aAddr[mt] + offA);
        #pragma unroll
        for (int p = 0; p < 4; ++p)
            ldsm_x4(bf[2 * p][0], bf[2 * p][1], bf[2 * p + 1][0], bf[2 * p + 1][1],
                    bAddr[p] + offB);
    };

    float acc[4][8][4];
    #pragma unroll
    for (int mt = 0; mt < 4; ++mt)
        #pragma unroll
        for (int nt = 0; nt < 8; ++nt)
            #pragma unroll
            for (int j = 0; j < 4; ++j) acc[mt][nt][j] = 0.f;

    auto mmaF = [&](unsigned (&af)[4][4], unsigned (&bf)[8][2]) {
        #pragma unroll
        for (int mt = 0; mt < 4; ++mt)
            #pragma unroll
            for (int nt = 0; nt < 8; ++nt)
                mma_f16(acc[mt][nt], af[mt], bf[nt]);
    };

    // prologue: stages 0,1 in flight; stage 0 ready; prime f0 with (0, ks0)
    stageLoad(0); stageLoad(1);
    cp_wait1();
    __syncthreads();
    ldF(af0, bf0, 0u, 0u);

    for (int kt = 0; kt < NKT; ++kt) {
        const unsigned soA = (unsigned)((kt % STAGES) * A_STAGE_B);
        const unsigned soB = (unsigned)((kt % STAGES) * B_STAGE_B);

        ldF(af1, bf1, soA + 32u, soB + 32u);          // ks1
        mmaF(af0, bf0);                               // ks0
        ldF(af0, bf0, soA + 64u, soB + 64u);          // ks2
        mmaF(af1, bf1);                               // ks1
        ldF(af1, bf1, soA + 96u, soB + 96u);          // ks3
        mmaF(af0, bf0);                               // ks2

        cp_wait0();          // stage kt+1 landed (this thread's groups)
        __syncthreads();     // visible CTA-wide; stage (kt+2)%3 free for overwrite

        if (kt + 2 < NKT) stageLoad(kt + 2);
        if (kt + 1 < NKT) {
            const unsigned nA = (unsigned)(((kt + 1) % STAGES) * A_STAGE_B);
            const unsigned nB = (unsigned)(((kt + 1) % STAGES) * B_STAGE_B);
            ldF(af0, bf0, nA, nB);                    // next tile ks0
        }
        mmaF(af1, bf1);                               // ks3
    }

    // epilogue
    #pragma unroll
    for (int mt = 0; mt < 4; ++mt) {
        int r0 = bM * 256 + wm * 64 + mt * 16 + g8;
        #pragma unroll
        for (int nt = 0; nt < 8; ++nt) {
            int col  = bN * 128 + wn * 64 + nt * 8 + qid * 2;
            int colL = wn * 64 + nt * 8 + qid * 2;
            if (MODE == 0) {
                float b0 = sBias[colL];
                float b1 = sBias[colL + 1];
                float x0 = acc[mt][nt][0] + b0;
                float x1 = acc[mt][nt][1] + b1;
                float x2 = acc[mt][nt][2] + b0;
                float x3 = acc[mt][nt][3] + b1;
                if (g8 == 0) {   // rows%8==0 are t==0: relu + fp16 h0
                    x0 = fmaxf(x0, 0.f); x1 = fmaxf(x1, 0.f);
                    x2 = fmaxf(x2, 0.f); x3 = fmaxf(x3, 0.f);
                    *(__half2*)(Hout + (size_t)r0 * ldH + col)       = __floats2half2_rn(x0, x1);
                    *(__half2*)(Hout + (size_t)(r0 + 8) * ldH + col) = __floats2half2_rn(x2, x3);
                }
                *(float2*)(C + (size_t)r0 * LDC + col)       = make_float2(x0, x1);
                *(float2*)(C + (size_t)(r0 + 8) * LDC + col) = make_float2(x2, x3);
            } else {
                float* p0 = C + (size_t)r0 * LDC + col;
                float* p1 = C + (size_t)(r0 + 8) * LDC + col;
                float2 g0 = *(float2*)p0;
                float2 g1 = *(float2*)p1;
                float x0 = fmaxf(acc[mt][nt][0] + g0.x, 0.f);
                float x1 = fmaxf(acc[mt][nt][1] + g0.y, 0.f);
                float x2 = fmaxf(acc[mt][nt][2] + g1.x, 0.f);
                float x3 = fmaxf(acc[mt][nt][3] + g1.y, 0.f);
                *(float2*)p0 = make_float2(x0, x1);
                *(float2*)p1 = make_float2(x2, x3);
                *(__half2*)(Hout + (size_t)r0 * ldH + col)       = __floats2half2_rn(x0, x1);
                *(__half2*)(Hout + (size_t)(r0 + 8) * ldH + col) = __floats2half2_rn(x2, x3);
            }
        }
    }
}

// pack two fp32 sources (widths 512 and 1024) into one fp16 row of 1536
template<int DST>  // 0 -> g_A16, 1 -> g_W16
__global__ void pack16(const float* __restrict__ s0, const float* __restrict__ s1, int rows)
{
    __half* dst = DST ? g_W16 : g_A16;
    size_t cid = (size_t)blockIdx.x * 256 + threadIdx.x;   // 8 cols each
    if (cid >= (size_t)rows * 192) return;
    int row = (int)(cid / 192);
    int c8  = (int)(cid % 192) * 8;
    const float* p = (c8 < 512) ? (s0 + (size_t)row * 512 + c8)
                                : (s1 + (size_t)row * 1024 + (c8 - 512));
    float4 v0 = ((const float4*)p)[0];
    float4 v1 = ((const float4*)p)[1];
    __half2 h0 = __floats2half2_rn(v0.x, v0.y);
    __half2 h1 = __floats2half2_rn(v0.z, v0.w);
    __half2 h2 = __floats2half2_rn(v1.x, v1.y);
    __half2 h3 = __floats2half2_rn(v1.z, v1.w);
    uint4 o = make_uint4(*(unsigned*)&h0, *(unsigned*)&h1, *(unsigned*)&h2, *(unsigned*)&h3);
    *(uint4*)(dst + (size_t)row * 1536 + c8) = o;
}

__global__ void cvt16(const float* __restrict__ src, int n)   // -> g_Wh16
{
    size_t i = ((size_t)blockIdx.x * 256 + threadIdx.x) * 8;
    if (i >= (size_t)n) return;
    float4 v0 = ((const float4*)(src + i))[0];
    float4 v1 = ((const float4*)(src + i))[1];
    __half2 h0 = __floats2half2_rn(v0.x, v0.y);
    __half2 h1 = __floats2half2_rn(v0.z, v0.w);
    __half2 h2 = __floats2half2_rn(v1.x, v1.y);
    __half2 h3 = __floats2half2_rn(v1.z, v1.w);
    *(uint4*)(g_Wh16 + i) = make_uint4(*(unsigned*)&h0, *(unsigned*)&h1,
                                       *(unsigned*)&h2, *(unsigned*)&h3);
}

// need[h, b] = out[b, 7, h]
__global__ void transpose_k(const float* __restrict__ out, float* __restrict__ need)
{
    __shared__ float tile[32][33];
    int h0 = blockIdx.x * 32;
    int b0 = blockIdx.y * 32;
    int x = threadIdx.x;
    int y = threadIdx.y;
    #pragma unroll
    for (int j = 0; j < 32; j += 8)
        tile[y + j][x] = out[(size_t)(b0 + y + j) * 8192 + 7168 + h0 + x];
    __syncthreads();
    #pragma unroll
    for (int j = 0; j < 32; j += 8)
        need[(size_t)(h0 + y + j) * 8192 + b0 + x] = tile[x][y + j];
}

extern "C" void kernel_launch(void* const* d_in, const int* in_sizes, int n_in,
                              void* d_out, int out_size)
{
    const float* entity   = (const float*)d_in[0];
    const float* relation = (const float*)d_in[1];
    const float* We       = (const float*)d_in[2];
    const float* be       = (const float*)d_in[3];
    const float* Wr       = (const float*)d_in[4];
    const float* br       = (const float*)d_in[5];
    const float* Wh       = (const float*)d_in[6];
    const float* bh       = (const float*)d_in[7];

    float* out  = (float*)d_out;               // [65536, 1024]
    float* need = out + (size_t)65536 * 1024;  // [1024, 8192]

    cudaFuncSetAttribute(gemm16<0>, cudaFuncAttributeMaxDynamicSharedMemorySize, SMEM_SZ);
    cudaFuncSetAttribute(gemm16<1>, cudaFuncAttributeMaxDynamicSharedMemorySize, SMEM_SZ);

    // prepass: fp16 conversions
    pack16<0><<<(int)(((size_t)65536 * 192 + 255) / 256), 256>>>(entity, relation, 65536);
    pack16<1><<<(1024 * 192 + 255) / 256, 256>>>(We, Wr, 1024);
    cvt16<<<(1024 * 1024 / 8 + 255) / 256, 256>>>(Wh, 1024 * 1024);

    // projection: M tiles = 256, N tiles = 8 (bN fastest -> A-block L2 reuse)
    gemm16<0><<<dim3(8, 256), 256, SMEM_SZ>>>(0, be, br, bh, out);

    // recurrence: M tiles = 32, N tiles = 8
    for (int t = 1; t < 8; ++t)
        gemm16<1><<<dim3(8, 32), 256, SMEM_SZ>>>(t, nullptr, nullptr, nullptr,
                                                 out + (size_t)t * 1024);

    transpose_k<<<dim3(32, 256), dim3(32, 8)>>>(out, need);
}

// round 11
// speedup vs baseline: 1.4458x; 1.4458x over previous
#include <cuda_runtime.h>
#include <cuda_fp16.h>
#include <cstdint>

// RNNModel: g = [E|R]@[We|Wr]^T + (be+br+bh)  (proj, relu on t==0 rows)
//           h_t = relu(g_t + h_{t-1}@Wh^T)    (7 in-place GEMM launches)
//           need = h_7^T
// R10: fragment double-buffer pipeline (proved tensor 71%) + register diet:
//      pointer-stepped cp.async addressing (compile-time immediates), running
//      stage index. CTA 256x128, warp 64x64, 3-stage cp.async, K-stage 64.
// NOTE: tcgen05 unusable in this harness build (ptxas targets compute_103 base).

#define STAGES    3
#define SROWB     144                   // bytes per smem row (64 halfs + pad)
#define A_STAGE_B (256 * SROWB)         // 36864
#define B_STAGE_B (128 * SROWB)         // 18432
#define A_REGION  (STAGES * A_STAGE_B)  // 110592
#define SMEM_SZ   (A_REGION + STAGES * B_STAGE_B + 512)   // 166400

// fp16 scratch (device-global: allocation-free)
__device__ __half g_A16[(size_t)65536 * 1536];   // packed [E|R]
__device__ __half g_W16[1024 * 1536];            // packed [We|Wr]
__device__ __half g_Wh16[1024 * 1024];
__device__ __half g_H16[(size_t)65536 * 1024];   // h_t fp16, same row indexing as out

__device__ __forceinline__ void mma_f16(float c[4], const unsigned a[4], const unsigned b[2]) {
    asm volatile(
        "mma.sync.aligned.m16n8k16.row.col.f32.f16.f16.f32 "
        "{%0,%1,%2,%3}, {%4,%5,%6,%7}, {%8,%9}, {%0,%1,%2,%3};\n"
        : "+f"(c[0]), "+f"(c[1]), "+f"(c[2]), "+f"(c[3])
        : "r"(a[0]), "r"(a[1]), "r"(a[2]), "r"(a[3]),
          "r"(b[0]), "r"(b[1]));
}
__device__ __forceinline__ void ldsm_x4(unsigned& r0, unsigned& r1, unsigned& r2, unsigned& r3,
                                        unsigned addr) {
    asm volatile("ldmatrix.sync.aligned.m8n8.x4.shared.b16 {%0,%1,%2,%3}, [%4];\n"
                 : "=r"(r0), "=r"(r1), "=r"(r2), "=r"(r3)
                 : "r"(addr));
}
__device__ __forceinline__ void cp16(unsigned dst, const __half* src) {
    asm volatile("cp.async.cg.shared.global [%0], [%1], 16;" :: "r"(dst), "l"(src));
}
__device__ __forceinline__ void cp_commit() {
    asm volatile("cp.async.commit_group;" ::: "memory");
}
__device__ __forceinline__ void cp_wait0() {
    asm volatile("cp.async.wait_group 0;" ::: "memory");
}
__device__ __forceinline__ void cp_wait1() {
    asm volatile("cp.async.wait_group 1;" ::: "memory");
}

// MODE 0: C[65536,1024] = A16 @ W16^T + bias; relu + H16 write on rows%8==0.
// MODE 1: C(+t*1024 by host) = relu(C + H16(t-1) @ Wh16^T); writes H16(t).
template<int MODE>
__global__ __launch_bounds__(256, 1)
void gemm16(int t, const float* __restrict__ be, const float* __restrict__ br,
            const float* __restrict__ bhp, float* C)
{
    constexpr int KTOT = MODE ? 1024 : 1536;
    constexpr int NKT  = KTOT / 64;
    constexpr int LDA  = MODE ? 8192 : 1536;
    constexpr int LDB  = MODE ? 1024 : 1536;
    constexpr int LDC  = MODE ? 8192 : 1024;

    extern __shared__ __align__(16) char sm[];
    float* sBias = (float*)(sm + A_REGION + STAGES * B_STAGE_B);
    const unsigned smBase = (unsigned)__cvta_generic_to_shared(sm);

    const int tid = threadIdx.x;
    const int bN  = blockIdx.x;
    const int bM  = blockIdx.y;

    const __half* A = MODE ? g_H16 + (size_t)(t - 1) * 1024 : g_A16;
    const __half* B = MODE ? g_Wh16 : g_W16;
    __half* Hout = MODE ? g_H16 + (size_t)t * 1024 : g_H16;
    const int ldH = MODE ? 8192 : 1024;

    if (MODE == 0) {
        if (tid < 128) {
            int c = bN * 128 + tid;
            sBias[tid] = be[c] + br[c] + bhp[c];
        }
    }

    const int lane = tid & 31;
    const int warp = tid >> 5;
    const int wm = warp & 3;      // 4 M-warps of 64 rows
    const int wn = warp >> 2;     // 2 N-warps of 64 cols
    const int g8  = lane >> 2;    // 0..7
    const int qid = lane & 3;

    // --- pointer-stepped cp.async state (all offsets compile-time) ---
    const int srow = tid >> 3;    // 0..31
    const int sch  = tid & 7;     // 16B chunk in row
    const __half* aG = A + (size_t)(bM * 256 + srow) * LDA + sch * 8;   // +i*32*LDA imm
    const __half* bG = B + (size_t)(bN * 128 + srow) * LDB + sch * 8;
    const unsigned dA0 = smBase + srow * SROWB + sch * 16;              // +i*32*SROWB imm
    const unsigned dB0 = smBase + A_REGION + srow * SROWB + sch * 16;
    int stIdx = 0;                // smem stage for next stageLoad (cycles 0..2)

    auto stageLoad = [&]() {
        const unsigned sA = dA0 + stIdx * A_STAGE_B;
        const unsigned sB = dB0 + stIdx * B_STAGE_B;
        #pragma unroll
        for (int i = 0; i < 8; ++i)
            cp16(sA + i * (32 * SROWB), aG + (size_t)i * 32 * LDA);
        #pragma unroll
        for (int i = 0; i < 4; ++i)
            cp16(sB + i * (32 * SROWB), bG + (size_t)i * 32 * LDB);
        cp_commit();
        aG += 64; bG += 64;
        stIdx = (stIdx == STAGES - 1) ? 0 : stIdx + 1;
    };

    // ldmatrix base addresses (stage 0)
    const int rA = wm * 64 + (lane & 7) + ((lane >> 3) & 1) * 8;
    const int kselA = (lane >> 4) & 1;
    const unsigned aAddr0 = smBase + (unsigned)(rA * SROWB + kselA * 16);
    const int rB = wn * 64 + (lane & 7) + ((lane >> 4) & 1) * 8;
    const int kselB = (lane >> 3) & 1;
    const unsigned bAddr0 = smBase + (unsigned)(A_REGION + rB * SROWB + kselB * 16);

    // fragment double buffer
    unsigned af0[4][4], af1[4][4], bf0[8][2], bf1[8][2];

    auto ldF = [&](unsigned (&af)[4][4], unsigned (&bf)[8][2], unsigned offA, unsigned offB) {
        #pragma unroll
        for (int mt = 0; mt < 4; ++mt)
            ldsm_x4(af[mt][0], af[mt][1], af[mt][2], af[mt][3],
                    aAddr0 + offA + mt * (16 * SROWB));
        #pragma unroll
        for (int p = 0; p < 4; ++p)
            ldsm_x4(bf[2 * p][0], bf[2 * p][1], bf[2 * p + 1][0], bf[2 * p + 1][1],
                    bAddr0 + offB + p * (16 * SROWB));
    };

    float acc[4][8][4];
    #pragma unroll
    for (int mt = 0; mt < 4; ++mt)
        #pragma unroll
        for (int nt = 0; nt < 8; ++nt)
            #pragma unroll
            for (int j = 0; j < 4; ++j) acc[mt][nt][j] = 0.f;

    auto mmaF = [&](unsigned (&af)[4][4], unsigned (&bf)[8][2]) {
        #pragma unroll
        for (int mt = 0; mt < 4; ++mt)
            #pragma unroll
            for (int nt = 0; nt < 8; ++nt)
                mma_f16(acc[mt][nt], af[mt], bf[nt]);
    };

    // prologue
    stageLoad(); stageLoad();
    cp_wait1();
    __syncthreads();
    ldF(af0, bf0, 0u, 0u);

    unsigned curA = 0, curB = 0;   // smem byte offsets of current stage
    for (int kt = 0; kt < NKT; ++kt) {
        ldF(af1, bf1, curA + 32u, curB + 32u);        // ks1
        mmaF(af0, bf0);                               // ks0
        ldF(af0, bf0, curA + 64u, curB + 64u);        // ks2
        mmaF(af1, bf1);                               // ks1
        ldF(af1, bf1, curA + 96u, curB + 96u);        // ks3
        mmaF(af0, bf0);                               // ks2

        cp_wait0();          // stage kt+1 landed
        __syncthreads();     // CTA-wide visibility; stage (kt+2)%3 reusable

        if (kt + 2 < NKT) stageLoad();
        curA = (curA == (STAGES - 1) * A_STAGE_B) ? 0u : curA + A_STAGE_B;
        curB = (curB == (STAGES - 1) * B_STAGE_B) ? 0u : curB + B_STAGE_B;
        if (kt + 1 < NKT) ldF(af0, bf0, curA, curB);  // next tile ks0
        mmaF(af1, bf1);                               // ks3
    }

    // epilogue
    #pragma unroll
    for (int mt = 0; mt < 4; ++mt) {
        int r0 = bM * 256 + wm * 64 + mt * 16 + g8;
        #pragma unroll
        for (int nt = 0; nt < 8; ++nt) {
            int col  = bN * 128 + wn * 64 + nt * 8 + qid * 2;
            int colL = wn * 64 + nt * 8 + qid * 2;
            if (MODE == 0) {
                float b0 = sBias[colL];
                float b1 = sBias[colL + 1];
                float x0 = acc[mt][nt][0] + b0;
                float x1 = acc[mt][nt][1] + b1;
                float x2 = acc[mt][nt][2] + b0;
                float x3 = acc[mt][nt][3] + b1;
                if (g8 == 0) {   // rows%8==0 are t==0: relu + fp16 h0
                    x0 = fmaxf(x0, 0.f); x1 = fmaxf(x1, 0.f);
                    x2 = fmaxf(x2, 0.f); x3 = fmaxf(x3, 0.f);
                    *(__half2*)(Hout + (size_t)r0 * ldH + col)       = __floats2half2_rn(x0, x1);
                    *(__half2*)(Hout + (size_t)(r0 + 8) * ldH + col) = __floats2half2_rn(x2, x3);
                }
                *(float2*)(C + (size_t)r0 * LDC + col)       = make_float2(x0, x1);
                *(float2*)(C + (size_t)(r0 + 8) * LDC + col) = make_float2(x2, x3);
            } else {
                float* p0 = C + (size_t)r0 * LDC + col;
                float* p1 = C + (size_t)(r0 + 8) * LDC + col;
                float2 g0 = *(float2*)p0;
                float2 g1 = *(float2*)p1;
                float x0 = fmaxf(acc[mt][nt][0] + g0.x, 0.f);
                float x1 = fmaxf(acc[mt][nt][1] + g0.y, 0.f);
                float x2 = fmaxf(acc[mt][nt][2] + g1.x, 0.f);
                float x3 = fmaxf(acc[mt][nt][3] + g1.y, 0.f);
                *(float2*)p0 = make_float2(x0, x1);
                *(float2*)p1 = make_float2(x2, x3);
                *(__half2*)(Hout + (size_t)r0 * ldH + col)       = __floats2half2_rn(x0, x1);
                *(__half2*)(Hout + (size_t)(r0 + 8) * ldH + col) = __floats2half2_rn(x2, x3);
            }
        }
    }
}

// pack two fp32 sources (widths 512 and 1024) into one fp16 row of 1536
template<int DST>  // 0 -> g_A16, 1 -> g_W16
__global__ void pack16(const float* __restrict__ s0, const float* __restrict__ s1, int rows)
{
    __half* dst = DST ? g_W16 : g_A16;
    size_t cid = (size_t)blockIdx.x * 256 + threadIdx.x;   // 8 cols each
    if (cid >= (size_t)rows * 192) return;
    int row = (int)(cid / 192);
    int c8  = (int)(cid % 192) * 8;
    const float* p = (c8 < 512) ? (s0 + (size_t)row * 512 + c8)
                                : (s1 + (size_t)row * 1024 + (c8 - 512));
    float4 v0 = ((const float4*)p)[0];
    float4 v1 = ((const float4*)p)[1];
    __half2 h0 = __floats2half2_rn(v0.x, v0.y);
    __half2 h1 = __floats2half2_rn(v0.z, v0.w);
    __half2 h2 = __floats2half2_rn(v1.x, v1.y);
    __half2 h3 = __floats2half2_rn(v1.z, v1.w);
    uint4 o = make_uint4(*(unsigned*)&h0, *(unsigned*)&h1, *(unsigned*)&h2, *(unsigned*)&h3);
    *(uint4*)(dst + (size_t)row * 1536 + c8) = o;
}

__global__ void cvt16(const float* __restrict__ src, int n)   // -> g_Wh16
{
    size_t i = ((size_t)blockIdx.x * 256 + threadIdx.x) * 8;
    if (i >= (size_t)n) return;
    float4 v0 = ((const float4*)(src + i))[0];
    float4 v1 = ((const float4*)(src + i))[1];
    __half2 h0 = __floats2half2_rn(v0.x, v0.y);
    __half2 h1 = __floats2half2_rn(v0.z, v0.w);
    __half2 h2 = __floats2half2_rn(v1.x, v1.y);
    __half2 h3 = __floats2half2_rn(v1.z, v1.w);
    *(uint4*)(g_Wh16 + i) = make_uint4(*(unsigned*)&h0, *(unsigned*)&h1,
                                       *(unsigned*)&h2, *(unsigned*)&h3);
}

// need[h, b] = out[b, 7, h]
__global__ void transpose_k(const float* __restrict__ out, float* __restrict__ need)
{
    __shared__ float tile[32][33];
    int h0 = blockIdx.x * 32;
    int b0 = blockIdx.y * 32;
    int x = threadIdx.x;
    int y = threadIdx.y;
    #pragma unroll
    for (int j = 0; j < 32; j += 8)
        tile[y + j][x] = out[(size_t)(b0 + y + j) * 8192 + 7168 + h0 + x];
    __syncthreads();
    #pragma unroll
    for (int j = 0; j < 32; j += 8)
        need[(size_t)(h0 + y + j) * 8192 + b0 + x] = tile[x][y + j];
}

extern "C" void kernel_launch(void* const* d_in, const int* in_sizes, int n_in,
                              void* d_out, int out_size)
{
    const float* entity   = (const float*)d_in[0];
    const float* relation = (const float*)d_in[1];
    const float* We       = (const float*)d_in[2];
    const float* be       = (const float*)d_in[3];
    const float* Wr       = (const float*)d_in[4];
    const float* br       = (const float*)d_in[5];
    const float* Wh       = (const float*)d_in[6];
    const float* bh       = (const float*)d_in[7];

    float* out  = (float*)d_out;               // [65536, 1024]
    float* need = out + (size_t)65536 * 1024;  // [1024, 8192]

    cudaFuncSetAttribute(gemm16<0>, cudaFuncAttributeMaxDynamicSharedMemorySize, SMEM_SZ);
    cudaFuncSetAttribute(gemm16<1>, cudaFuncAttributeMaxDynamicSharedMemorySize, SMEM_SZ);

    // prepass: fp16 conversions
    pack16<0><<<(int)(((size_t)65536 * 192 + 255) / 256), 256>>>(entity, relation, 65536);
    pack16<1><<<(1024 * 192 + 255) / 256, 256>>>(We, Wr, 1024);
    cvt16<<<(1024 * 1024 / 8 + 255) / 256, 256>>>(Wh, 1024 * 1024);

    // projection: M tiles = 256, N tiles = 8 (bN fastest -> A-block L2 reuse)
    gemm16<0><<<dim3(8, 256), 256, SMEM_SZ>>>(0, be, br, bh, out);

    // recurrence: M tiles = 32, N tiles = 8
    for (int t = 1; t < 8; ++t)
        gemm16<1><<<dim3(8, 32), 256, SMEM_SZ>>>(t, nullptr, nullptr, nullptr,
                                                 out + (size_t)t * 1024);

    transpose_k<<<dim3(32, 256), dim3(32, 8)>>>(out, need);
}

// round 12
// speedup vs baseline: 1.4898x; 1.0304x over previous
#include <cuda_runtime.h>
#include <cuda_fp16.h>
#include <cstdint>

// RNNModel: g = [E|R]@[We|Wr]^T + (be+br+bh)  (proj, relu on t==0 rows)
//           h_t = relu(g_t + h_{t-1}@Wh^T)    (7 in-place GEMM launches)
//           need = h_7^T
// R11 (best: 1094us, proj 491us @ tensor 69.4%) + R12: mma ks3 issued BEFORE the
//     per-tile barrier so the HMMA backlog drains under cp_wait0/__syncthreads;
//     prepass pack without integer division.
// NOTE: tcgen05 unusable in this harness build (ptxas targets compute_103 base).

#define STAGES    3
#define SROWB     144                   // bytes per smem row (64 halfs + pad)
#define A_STAGE_B (256 * SROWB)         // 36864
#define B_STAGE_B (128 * SROWB)         // 18432
#define A_REGION  (STAGES * A_STAGE_B)  // 110592
#define SMEM_SZ   (A_REGION + STAGES * B_STAGE_B + 512)   // 166400

// fp16 scratch (device-global: allocation-free)
__device__ __half g_A16[(size_t)65536 * 1536];   // packed [E|R]
__device__ __half g_W16[1024 * 1536];            // packed [We|Wr]
__device__ __half g_Wh16[1024 * 1024];
__device__ __half g_H16[(size_t)65536 * 1024];   // h_t fp16, same row indexing as out

__device__ __forceinline__ void mma_f16(float c[4], const unsigned a[4], const unsigned b[2]) {
    asm volatile(
        "mma.sync.aligned.m16n8k16.row.col.f32.f16.f16.f32 "
        "{%0,%1,%2,%3}, {%4,%5,%6,%7}, {%8,%9}, {%0,%1,%2,%3};\n"
        : "+f"(c[0]), "+f"(c[1]), "+f"(c[2]), "+f"(c[3])
        : "r"(a[0]), "r"(a[1]), "r"(a[2]), "r"(a[3]),
          "r"(b[0]), "r"(b[1]));
}
__device__ __forceinline__ void ldsm_x4(unsigned& r0, unsigned& r1, unsigned& r2, unsigned& r3,
                                        unsigned addr) {
    asm volatile("ldmatrix.sync.aligned.m8n8.x4.shared.b16 {%0,%1,%2,%3}, [%4];\n"
                 : "=r"(r0), "=r"(r1), "=r"(r2), "=r"(r3)
                 : "r"(addr));
}
__device__ __forceinline__ void cp16(unsigned dst, const __half* src) {
    asm volatile("cp.async.cg.shared.global [%0], [%1], 16;" :: "r"(dst), "l"(src));
}
__device__ __forceinline__ void cp_commit() {
    asm volatile("cp.async.commit_group;" ::: "memory");
}
__device__ __forceinline__ void cp_wait0() {
    asm volatile("cp.async.wait_group 0;" ::: "memory");
}
__device__ __forceinline__ void cp_wait1() {
    asm volatile("cp.async.wait_group 1;" ::: "memory");
}

// MODE 0: C[65536,1024] = A16 @ W16^T + bias; relu + H16 write on rows%8==0.
// MODE 1: C(+t*1024 by host) = relu(C + H16(t-1) @ Wh16^T); writes H16(t).
template<int MODE>
__global__ __launch_bounds__(256, 1)
void gemm16(int t, const float* __restrict__ be, const float* __restrict__ br,
            const float* __restrict__ bhp, float* C)
{
    constexpr int KTOT = MODE ? 1024 : 1536;
    constexpr int NKT  = KTOT / 64;
    constexpr int LDA  = MODE ? 8192 : 1536;
    constexpr int LDB  = MODE ? 1024 : 1536;
    constexpr int LDC  = MODE ? 8192 : 1024;

    extern __shared__ __align__(16) char sm[];
    float* sBias = (float*)(sm + A_REGION + STAGES * B_STAGE_B);
    const unsigned smBase = (unsigned)__cvta_generic_to_shared(sm);

    const int tid = threadIdx.x;
    const int bN  = blockIdx.x;
    const int bM  = blockIdx.y;

    const __half* A = MODE ? g_H16 + (size_t)(t - 1) * 1024 : g_A16;
    const __half* B = MODE ? g_Wh16 : g_W16;
    __half* Hout = MODE ? g_H16 + (size_t)t * 1024 : g_H16;
    const int ldH = MODE ? 8192 : 1024;

    if (MODE == 0) {
        if (tid < 128) {
            int c = bN * 128 + tid;
            sBias[tid] = be[c] + br[c] + bhp[c];
        }
    }

    const int lane = tid & 31;
    const int warp = tid >> 5;
    const int wm = warp & 3;      // 4 M-warps of 64 rows
    const int wn = warp >> 2;     // 2 N-warps of 64 cols
    const int g8  = lane >> 2;    // 0..7
    const int qid = lane & 3;

    // --- pointer-stepped cp.async state (all offsets compile-time) ---
    const int srow = tid >> 3;    // 0..31
    const int sch  = tid & 7;     // 16B chunk in row
    const __half* aG = A + (size_t)(bM * 256 + srow) * LDA + sch * 8;
    const __half* bG = B + (size_t)(bN * 128 + srow) * LDB + sch * 8;
    const unsigned dA0 = smBase + srow * SROWB + sch * 16;
    const unsigned dB0 = smBase + A_REGION + srow * SROWB + sch * 16;
    int stIdx = 0;

    auto stageLoad = [&]() {
        const unsigned sA = dA0 + stIdx * A_STAGE_B;
        const unsigned sB = dB0 + stIdx * B_STAGE_B;
        #pragma unroll
        for (int i = 0; i < 8; ++i)
            cp16(sA + i * (32 * SROWB), aG + (size_t)i * 32 * LDA);
        #pragma unroll
        for (int i = 0; i < 4; ++i)
            cp16(sB + i * (32 * SROWB), bG + (size_t)i * 32 * LDB);
        cp_commit();
        aG += 64; bG += 64;
        stIdx = (stIdx == STAGES - 1) ? 0 : stIdx + 1;
    };

    // ldmatrix base addresses (stage 0)
    const int rA = wm * 64 + (lane & 7) + ((lane >> 3) & 1) * 8;
    const int kselA = (lane >> 4) & 1;
    const unsigned aAddr0 = smBase + (unsigned)(rA * SROWB + kselA * 16);
    const int rB = wn * 64 + (lane & 7) + ((lane >> 4) & 1) * 8;
    const int kselB = (lane >> 3) & 1;
    const unsigned bAddr0 = smBase + (unsigned)(A_REGION + rB * SROWB + kselB * 16);

    // fragment double buffer
    unsigned af0[4][4], af1[4][4], bf0[8][2], bf1[8][2];

    auto ldF = [&](unsigned (&af)[4][4], unsigned (&bf)[8][2], unsigned offA, unsigned offB) {
        #pragma unroll
        for (int mt = 0; mt < 4; ++mt)
            ldsm_x4(af[mt][0], af[mt][1], af[mt][2], af[mt][3],
                    aAddr0 + offA + mt * (16 * SROWB));
        #pragma unroll
        for (int p = 0; p < 4; ++p)
            ldsm_x4(bf[2 * p][0], bf[2 * p][1], bf[2 * p + 1][0], bf[2 * p + 1][1],
                    bAddr0 + offB + p * (16 * SROWB));
    };

    float acc[4][8][4];
    #pragma unroll
    for (int mt = 0; mt < 4; ++mt)
        #pragma unroll
        for (int nt = 0; nt < 8; ++nt)
            #pragma unroll
            for (int j = 0; j < 4; ++j) acc[mt][nt][j] = 0.f;

    auto mmaF = [&](unsigned (&af)[4][4], unsigned (&bf)[8][2]) {
        #pragma unroll
        for (int mt = 0; mt < 4; ++mt)
            #pragma unroll
            for (int nt = 0; nt < 8; ++nt)
                mma_f16(acc[mt][nt], af[mt], bf[nt]);
    };

    // prologue
    stageLoad(); stageLoad();
    cp_wait1();
    __syncthreads();
    ldF(af0, bf0, 0u, 0u);

    unsigned curA = 0, curB = 0;
    for (int kt = 0; kt < NKT; ++kt) {
        ldF(af1, bf1, curA + 32u, curB + 32u);        // ks1
        mmaF(af0, bf0);                               // ks0
        ldF(af0, bf0, curA + 64u, curB + 64u);        // ks2
        mmaF(af1, bf1);                               // ks1
        ldF(af1, bf1, curA + 96u, curB + 96u);        // ks3
        mmaF(af0, bf0);                               // ks2
        mmaF(af1, bf1);                               // ks3 — queue full backlog

        cp_wait0();          // barrier latency hides under HMMA drain
        __syncthreads();

        if (kt + 2 < NKT) stageLoad();
        curA = (curA == (STAGES - 1) * A_STAGE_B) ? 0u : curA + A_STAGE_B;
        curB = (curB == (STAGES - 1) * B_STAGE_B) ? 0u : curB + B_STAGE_B;
        if (kt + 1 < NKT) ldF(af0, bf0, curA, curB);  // next tile ks0
    }

    // epilogue
    #pragma unroll
    for (int mt = 0; mt < 4; ++mt) {
        int r0 = bM * 256 + wm * 64 + mt * 16 + g8;
        #pragma unroll
        for (int nt = 0; nt < 8; ++nt) {
            int col  = bN * 128 + wn * 64 + nt * 8 + qid * 2;
            int colL = wn * 64 + nt * 8 + qid * 2;
            if (MODE == 0) {
                float b0 = sBias[colL];
                float b1 = sBias[colL + 1];
                float x0 = acc[mt][nt][0] + b0;
                float x1 = acc[mt][nt][1] + b1;
                float x2 = acc[mt][nt][2] + b0;
                float x3 = acc[mt][nt][3] + b1;
                if (g8 == 0) {   // rows%8==0 are t==0: relu + fp16 h0
                    x0 = fmaxf(x0, 0.f); x1 = fmaxf(x1, 0.f);
                    x2 = fmaxf(x2, 0.f); x3 = fmaxf(x3, 0.f);
                    *(__half2*)(Hout + (size_t)r0 * ldH + col)       = __floats2half2_rn(x0, x1);
                    *(__half2*)(Hout + (size_t)(r0 + 8) * ldH + col) = __floats2half2_rn(x2, x3);
                }
                *(float2*)(C + (size_t)r0 * LDC + col)       = make_float2(x0, x1);
                *(float2*)(C + (size_t)(r0 + 8) * LDC + col) = make_float2(x2, x3);
            } else {
                float* p0 = C + (size_t)r0 * LDC + col;
                float* p1 = C + (size_t)(r0 + 8) * LDC + col;
                float2 g0 = *(float2*)p0;
                float2 g1 = *(float2*)p1;
                float x0 = fmaxf(acc[mt][nt][0] + g0.x, 0.f);
                float x1 = fmaxf(acc[mt][nt][1] + g0.y, 0.f);
                float x2 = fmaxf(acc[mt][nt][2] + g1.x, 0.f);
                float x3 = fmaxf(acc[mt][nt][3] + g1.y, 0.f);
                *(float2*)p0 = make_float2(x0, x1);
                *(float2*)p1 = make_float2(x2, x3);
                *(__half2*)(Hout + (size_t)r0 * ldH + col)       = __floats2half2_rn(x0, x1);
                *(__half2*)(Hout + (size_t)(r0 + 8) * ldH + col) = __floats2half2_rn(x2, x3);
            }
        }
    }
}

// pack two fp32 sources (widths 512 and 1024) into one fp16 row of 1536.
// One row per block, 192 threads, no integer division.
template<int DST>  // 0 -> g_A16, 1 -> g_W16
__global__ void pack16(const float* __restrict__ s0, const float* __restrict__ s1)
{
    __half* dst = DST ? g_W16 : g_A16;
    const int row = blockIdx.x;
    const int c8  = threadIdx.x * 8;
    const float* p = (c8 < 512) ? (s0 + (size_t)row * 512 + c8)
                                : (s1 + (size_t)row * 1024 + (c8 - 512));
    float4 v0 = ((const float4*)p)[0];
    float4 v1 = ((const float4*)p)[1];
    __half2 h0 = __floats2half2_rn(make_float2(v0.x, v0.y).x, v0.y);
    h0 = __floats2half2_rn(v0.x, v0.y);
    __half2 h1 = __floats2half2_rn(v0.z, v0.w);
    __half2 h2 = __floats2half2_rn(v1.x, v1.y);
    __half2 h3 = __floats2half2_rn(v1.z, v1.w);
    uint4 o = make_uint4(*(unsigned*)&h0, *(unsigned*)&h1, *(unsigned*)&h2, *(unsigned*)&h3);
    *(uint4*)(dst + (size_t)row * 1536 + c8) = o;
}

__global__ void cvt16(const float* __restrict__ src, int n)   // -> g_Wh16
{
    size_t i = ((size_t)blockIdx.x * 256 + threadIdx.x) * 8;
    if (i >= (size_t)n) return;
    float4 v0 = ((const float4*)(src + i))[0];
    float4 v1 = ((const float4*)(src + i))[1];
    __half2 h0 = __floats2half2_rn(v0.x, v0.y);
    __half2 h1 = __floats2half2_rn(v0.z, v0.w);
    __half2 h2 = __floats2half2_rn(v1.x, v1.y);
    __half2 h3 = __floats2half2_rn(v1.z, v1.w);
    *(uint4*)(g_Wh16 + i) = make_uint4(*(unsigned*)&h0, *(unsigned*)&h1,
                                       *(unsigned*)&h2, *(unsigned*)&h3);
}

// need[h, b] = out[b, 7, h]
__global__ void transpose_k(const float* __restrict__ out, float* __restrict__ need)
{
    __shared__ float tile[32][33];
    int h0 = blockIdx.x * 32;
    int b0 = blockIdx.y * 32;
    int x = threadIdx.x;
    int y = threadIdx.y;
    #pragma unroll
    for (int j = 0; j < 32; j += 8)
        tile[y + j][x] = out[(size_t)(b0 + y + j) * 8192 + 7168 + h0 + x];
    __syncthreads();
    #pragma unroll
    for (int j = 0; j < 32; j += 8)
        need[(size_t)(h0 + y + j) * 8192 + b0 + x] = tile[x][y + j];
}

extern "C" void kernel_launch(void* const* d_in, const int* in_sizes, int n_in,
                              void* d_out, int out_size)
{
    const float* entity   = (const float*)d_in[0];
    const float* relation = (const float*)d_in[1];
    const float* We       = (const float*)d_in[2];
    const float* be       = (const float*)d_in[3];
    const float* Wr       = (const float*)d_in[4];
    const float* br       = (const float*)d_in[5];
    const float* Wh       = (const float*)d_in[6];
    const float* bh       = (const float*)d_in[7];

    float* out  = (float*)d_out;               // [65536, 1024]
    float* need = out + (size_t)65536 * 1024;  // [1024, 8192]

    cudaFuncSetAttribute(gemm16<0>, cudaFuncAttributeMaxDynamicSharedMemorySize, SMEM_SZ);
    cudaFuncSetAttribute(gemm16<1>, cudaFuncAttributeMaxDynamicSharedMemorySize, SMEM_SZ);

    // prepass: fp16 conversions
    pack16<0><<<65536, 192>>>(entity, relation);
    pack16<1><<<1024, 192>>>(We, Wr);
    cvt16<<<(1024 * 1024 / 8 + 255) / 256, 256>>>(Wh, 1024 * 1024);

    // projection: M tiles = 256, N tiles = 8 (bN fastest -> A-block L2 reuse)
    gemm16<0><<<dim3(8, 256), 256, SMEM_SZ>>>(0, be, br, bh, out);

    // recurrence: M tiles = 32, N tiles = 8
    for (int t = 1; t < 8; ++t)
        gemm16<1><<<dim3(8, 32), 256, SMEM_SZ>>>(t, nullptr, nullptr, nullptr,
                                                 out + (size_t)t * 1024);

    transpose_k<<<dim3(32, 256), dim3(32, 8)>>>(out, need);
}

// round 13
// speedup vs baseline: 1.5355x; 1.0307x over previous
#include <cuda_runtime.h>
#include <cuda_fp16.h>
#include <cstdint>

// RNNModel: g = [E|R]@[We|Wr]^T + (be+br+bh)  (proj, relu on t==0 rows)
//           h_t = relu(g_t + h_{t-1}@Wh^T)    (7 in-place GEMM launches)
//           need = h_7^T
// R12 (best: 1062us, proj 472us @ tensor 72.6%) + R13: stageLoad issued
//     mid-tile under the MMA shadow; cp_wait1 with 2-iteration latency cover;
//     post-barrier path = one ldF only.
// NOTE: tcgen05 unusable in this harness build (ptxas targets compute_103 base).

#define STAGES    3
#define SROWB     144                   // bytes per smem row (64 halfs + pad)
#define A_STAGE_B (256 * SROWB)         // 36864
#define B_STAGE_B (128 * SROWB)         // 18432
#define A_REGION  (STAGES * A_STAGE_B)  // 110592
#define SMEM_SZ   (A_REGION + STAGES * B_STAGE_B + 512)   // 166400

// fp16 scratch (device-global: allocation-free)
__device__ __half g_A16[(size_t)65536 * 1536];   // packed [E|R]
__device__ __half g_W16[1024 * 1536];            // packed [We|Wr]
__device__ __half g_Wh16[1024 * 1024];
__device__ __half g_H16[(size_t)65536 * 1024];   // h_t fp16, same row indexing as out

__device__ __forceinline__ void mma_f16(float c[4], const unsigned a[4], const unsigned b[2]) {
    asm volatile(
        "mma.sync.aligned.m16n8k16.row.col.f32.f16.f16.f32 "
        "{%0,%1,%2,%3}, {%4,%5,%6,%7}, {%8,%9}, {%0,%1,%2,%3};\n"
        : "+f"(c[0]), "+f"(c[1]), "+f"(c[2]), "+f"(c[3])
        : "r"(a[0]), "r"(a[1]), "r"(a[2]), "r"(a[3]),
          "r"(b[0]), "r"(b[1]));
}
__device__ __forceinline__ void ldsm_x4(unsigned& r0, unsigned& r1, unsigned& r2, unsigned& r3,
                                        unsigned addr) {
    asm volatile("ldmatrix.sync.aligned.m8n8.x4.shared.b16 {%0,%1,%2,%3}, [%4];\n"
                 : "=r"(r0), "=r"(r1), "=r"(r2), "=r"(r3)
                 : "r"(addr));
}
__device__ __forceinline__ void cp16(unsigned dst, const __half* src) {
    asm volatile("cp.async.cg.shared.global [%0], [%1], 16;" :: "r"(dst), "l"(src));
}
__device__ __forceinline__ void cp_commit() {
    asm volatile("cp.async.commit_group;" ::: "memory");
}
__device__ __forceinline__ void cp_wait1() {
    asm volatile("cp.async.wait_group 1;" ::: "memory");
}

// MODE 0: C[65536,1024] = A16 @ W16^T + bias; relu + H16 write on rows%8==0.
// MODE 1: C(+t*1024 by host) = relu(C + H16(t-1) @ Wh16^T); writes H16(t).
template<int MODE>
__global__ __launch_bounds__(256, 1)
void gemm16(int t, const float* __restrict__ be, const float* __restrict__ br,
            const float* __restrict__ bhp, float* C)
{
    constexpr int KTOT = MODE ? 1024 : 1536;
    constexpr int NKT  = KTOT / 64;
    constexpr int LDA  = MODE ? 8192 : 1536;
    constexpr int LDB  = MODE ? 1024 : 1536;
    constexpr int LDC  = MODE ? 8192 : 1024;

    extern __shared__ __align__(16) char sm[];
    float* sBias = (float*)(sm + A_REGION + STAGES * B_STAGE_B);
    const unsigned smBase = (unsigned)__cvta_generic_to_shared(sm);

    const int tid = threadIdx.x;
    const int bN  = blockIdx.x;
    const int bM  = blockIdx.y;

    const __half* A = MODE ? g_H16 + (size_t)(t - 1) * 1024 : g_A16;
    const __half* B = MODE ? g_Wh16 : g_W16;
    __half* Hout = MODE ? g_H16 + (size_t)t * 1024 : g_H16;
    const int ldH = MODE ? 8192 : 1024;

    if (MODE == 0) {
        if (tid < 128) {
            int c = bN * 128 + tid;
            sBias[tid] = be[c] + br[c] + bhp[c];
        }
    }

    const int lane = tid & 31;
    const int warp = tid >> 5;
    const int wm = warp & 3;      // 4 M-warps of 64 rows
    const int wn = warp >> 2;     // 2 N-warps of 64 cols
    const int g8  = lane >> 2;    // 0..7
    const int qid = lane & 3;

    // --- pointer-stepped cp.async state (all offsets compile-time) ---
    const int srow = tid >> 3;    // 0..31
    const int sch  = tid & 7;     // 16B chunk in row
    const __half* aG = A + (size_t)(bM * 256 + srow) * LDA + sch * 8;
    const __half* bG = B + (size_t)(bN * 128 + srow) * LDB + sch * 8;
    const unsigned dA0 = smBase + srow * SROWB + sch * 16;
    const unsigned dB0 = smBase + A_REGION + srow * SROWB + sch * 16;
    int stIdx = 0;

    auto stageLoad = [&]() {
        const unsigned sA = dA0 + stIdx * A_STAGE_B;
        const unsigned sB = dB0 + stIdx * B_STAGE_B;
        #pragma unroll
        for (int i = 0; i < 8; ++i)
            cp16(sA + i * (32 * SROWB), aG + (size_t)i * 32 * LDA);
        #pragma unroll
        for (int i = 0; i < 4; ++i)
            cp16(sB + i * (32 * SROWB), bG + (size_t)i * 32 * LDB);
        cp_commit();
        aG += 64; bG += 64;
        stIdx = (stIdx == STAGES - 1) ? 0 : stIdx + 1;
    };

    // ldmatrix base addresses (stage 0)
    const int rA = wm * 64 + (lane & 7) + ((lane >> 3) & 1) * 8;
    const int kselA = (lane >> 4) & 1;
    const unsigned aAddr0 = smBase + (unsigned)(rA * SROWB + kselA * 16);
    const int rB = wn * 64 + (lane & 7) + ((lane >> 4) & 1) * 8;
    const int kselB = (lane >> 3) & 1;
    const unsigned bAddr0 = smBase + (unsigned)(A_REGION + rB * SROWB + kselB * 16);

    // fragment double buffer
    unsigned af0[4][4], af1[4][4], bf0[8][2], bf1[8][2];

    auto ldF = [&](unsigned (&af)[4][4], unsigned (&bf)[8][2], unsigned offA, unsigned offB) {
        #pragma unroll
        for (int mt = 0; mt < 4; ++mt)
            ldsm_x4(af[mt][0], af[mt][1], af[mt][2], af[mt][3],
                    aAddr0 + offA + mt * (16 * SROWB));
        #pragma unroll
        for (int p = 0; p < 4; ++p)
            ldsm_x4(bf[2 * p][0], bf[2 * p][1], bf[2 * p + 1][0], bf[2 * p + 1][1],
                    bAddr0 + offB + p * (16 * SROWB));
    };

    float acc[4][8][4];
    #pragma unroll
    for (int mt = 0; mt < 4; ++mt)
        #pragma unroll
        for (int nt = 0; nt < 8; ++nt)
            #pragma unroll
            for (int j = 0; j < 4; ++j) acc[mt][nt][j] = 0.f;

    auto mmaF = [&](unsigned (&af)[4][4], unsigned (&bf)[8][2]) {
        #pragma unroll
        for (int mt = 0; mt < 4; ++mt)
            #pragma unroll
            for (int nt = 0; nt < 8; ++nt)
                mma_f16(acc[mt][nt], af[mt], bf[nt]);
    };

    // prologue: stages 0,1 issued; stage 0 guaranteed (wait1)
    stageLoad(); stageLoad();
    cp_wait1();
    __syncthreads();
    ldF(af0, bf0, 0u, 0u);

    unsigned curA = 0, curB = 0;
    for (int kt = 0; kt < NKT; ++kt) {
        ldF(af1, bf1, curA + 32u, curB + 32u);        // ks1
        mmaF(af0, bf0);                               // ks0
        if (kt + 2 < NKT) stageLoad();                // issued under MMA shadow
        else cp_commit();                             // keep group accounting in order
        ldF(af0, bf0, curA + 64u, curB + 64u);        // ks2
        mmaF(af1, bf1);                               // ks1
        ldF(af1, bf1, curA + 96u, curB + 96u);        // ks3
        mmaF(af0, bf0);                               // ks2
        mmaF(af1, bf1);                               // ks3 — full backlog queued

        cp_wait1();          // stage kt+1 done (2-iter-old); kt+2 may still fly
        __syncthreads();     // hides under HMMA drain

        curA = (curA == (STAGES - 1) * A_STAGE_B) ? 0u : curA + A_STAGE_B;
        curB = (curB == (STAGES - 1) * B_STAGE_B) ? 0u : curB + B_STAGE_B;
        if (kt + 1 < NKT) ldF(af0, bf0, curA, curB);  // next tile ks0 (only exposed op)
    }

    // epilogue
    #pragma unroll
    for (int mt = 0; mt < 4; ++mt) {
        int r0 = bM * 256 + wm * 64 + mt * 16 + g8;
        #pragma unroll
        for (int nt = 0; nt < 8; ++nt) {
            int col  = bN * 128 + wn * 64 + nt * 8 + qid * 2;
            int colL = wn * 64 + nt * 8 + qid * 2;
            if (MODE == 0) {
                float b0 = sBias[colL];
                float b1 = sBias[colL + 1];
                float x0 = acc[mt][nt][0] + b0;
                float x1 = acc[mt][nt][1] + b1;
                float x2 = acc[mt][nt][2] + b0;
                float x3 = acc[mt][nt][3] + b1;
                if (g8 == 0) {   // rows%8==0 are t==0: relu + fp16 h0
                    x0 = fmaxf(x0, 0.f); x1 = fmaxf(x1, 0.f);
                    x2 = fmaxf(x2, 0.f); x3 = fmaxf(x3, 0.f);
                    *(__half2*)(Hout + (size_t)r0 * ldH + col)       = __floats2half2_rn(x0, x1);
                    *(__half2*)(Hout + (size_t)(r0 + 8) * ldH + col) = __floats2half2_rn(x2, x3);
                }
                *(float2*)(C + (size_t)r0 * LDC + col)       = make_float2(x0, x1);
                *(float2*)(C + (size_t)(r0 + 8) * LDC + col) = make_float2(x2, x3);
            } else {
                float* p0 = C + (size_t)r0 * LDC + col;
                float* p1 = C + (size_t)(r0 + 8) * LDC + col;
                float2 g0 = *(float2*)p0;
                float2 g1 = *(float2*)p1;
                float x0 = fmaxf(acc[mt][nt][0] + g0.x, 0.f);
                float x1 = fmaxf(acc[mt][nt][1] + g0.y, 0.f);
                float x2 = fmaxf(acc[mt][nt][2] + g1.x, 0.f);
                float x3 = fmaxf(acc[mt][nt][3] + g1.y, 0.f);
                *(float2*)p0 = make_float2(x0, x1);
                *(float2*)p1 = make_float2(x2, x3);
                *(__half2*)(Hout + (size_t)r0 * ldH + col)       = __floats2half2_rn(x0, x1);
                *(__half2*)(Hout + (size_t)(r0 + 8) * ldH + col) = __floats2half2_rn(x2, x3);
            }
        }
    }
}

// pack two fp32 sources (widths 512 and 1024) into one fp16 row of 1536.
// One row per block, 192 threads, no integer division.
template<int DST>  // 0 -> g_A16, 1 -> g_W16
__global__ void pack16(const float* __restrict__ s0, const float* __restrict__ s1)
{
    __half* dst = DST ? g_W16 : g_A16;
    const int row = blockIdx.x;
    const int c8  = threadIdx.x * 8;
    const float* p = (c8 < 512) ? (s0 + (size_t)row * 512 + c8)
                                : (s1 + (size_t)row * 1024 + (c8 - 512));
    float4 v0 = ((const float4*)p)[0];
    float4 v1 = ((const float4*)p)[1];
    __half2 h0 = __floats2half2_rn(v0.x, v0.y);
    __half2 h1 = __floats2half2_rn(v0.z, v0.w);
    __half2 h2 = __floats2half2_rn(v1.x, v1.y);
    __half2 h3 = __floats2half2_rn(v1.z, v1.w);
    uint4 o = make_uint4(*(unsigned*)&h0, *(unsigned*)&h1, *(unsigned*)&h2, *(unsigned*)&h3);
    *(uint4*)(dst + (size_t)row * 1536 + c8) = o;
}

__global__ void cvt16(const float* __restrict__ src, int n)   // -> g_Wh16
{
    size_t i = ((size_t)blockIdx.x * 256 + threadIdx.x) * 8;
    if (i >= (size_t)n) return;
    float4 v0 = ((const float4*)(src + i))[0];
    float4 v1 = ((const float4*)(src + i))[1];
    __half2 h0 = __floats2half2_rn(v0.x, v0.y);
    __half2 h1 = __floats2half2_rn(v0.z, v0.w);
    __half2 h2 = __floats2half2_rn(v1.x, v1.y);
    __half2 h3 = __floats2half2_rn(v1.z, v1.w);
    *(uint4*)(g_Wh16 + i) = make_uint4(*(unsigned*)&h0, *(unsigned*)&h1,
                                       *(unsigned*)&h2, *(unsigned*)&h3);
}

// need[h, b] = out[b, 7, h]
__global__ void transpose_k(const float* __restrict__ out, float* __restrict__ need)
{
    __shared__ float tile[32][33];
    int h0 = blockIdx.x * 32;
    int b0 = blockIdx.y * 32;
    int x = threadIdx.x;
    int y = threadIdx.y;
    #pragma unroll
    for (int j = 0; j < 32; j += 8)
        tile[y + j][x] = out[(size_t)(b0 + y + j) * 8192 + 7168 + h0 + x];
    __syncthreads();
    #pragma unroll
    for (int j = 0; j < 32; j += 8)
        need[(size_t)(h0 + y + j) * 8192 + b0 + x] = tile[x][y + j];
}

extern "C" void kernel_launch(void* const* d_in, const int* in_sizes, int n_in,
                              void* d_out, int out_size)
{
    const float* entity   = (const float*)d_in[0];
    const float* relation = (const float*)d_in[1];
    const float* We       = (const float*)d_in[2];
    const float* be       = (const float*)d_in[3];
    const float* Wr       = (const float*)d_in[4];
    const float* br       = (const float*)d_in[5];
    const float* Wh       = (const float*)d_in[6];
    const float* bh       = (const float*)d_in[7];

    float* out  = (float*)d_out;               // [65536, 1024]
    float* need = out + (size_t)65536 * 1024;  // [1024, 8192]

    cudaFuncSetAttribute(gemm16<0>, cudaFuncAttributeMaxDynamicSharedMemorySize, SMEM_SZ);
    cudaFuncSetAttribute(gemm16<1>, cudaFuncAttributeMaxDynamicSharedMemorySize, SMEM_SZ);

    // prepass: fp16 conversions
    pack16<0><<<65536, 192>>>(entity, relation);
    pack16<1><<<1024, 192>>>(We, Wr);
    cvt16<<<(1024 * 1024 / 8 + 255) / 256, 256>>>(Wh, 1024 * 1024);

    // projection: M tiles = 256, N tiles = 8 (bN fastest -> A-block L2 reuse)
    gemm16<0><<<dim3(8, 256), 256, SMEM_SZ>>>(0, be, br, bh, out);

    // recurrence: M tiles = 32, N tiles = 8
    for (int t = 1; t < 8; ++t)
        gemm16<1><<<dim3(8, 32), 256, SMEM_SZ>>>(t, nullptr, nullptr, nullptr,
                                                 out + (size_t)t * 1024);

    transpose_k<<<dim3(32, 256), dim3(32, 8)>>>(out, need);
}